// round 2
// baseline (speedup 1.0000x reference)
#include <cuda_runtime.h>

#define NN   50000
#define NE   800000
#define NEDG (NE + NN)
#define NG   512
#define CH   64

// ---------------- scratch (device globals; no allocations allowed) ----------
__device__ float g_h[NN * CH];     // per-layer h = X @ W
__device__ float g_out[NN * CH];   // per-layer aggregated + elu output
__device__ float g_as[NN];
__device__ float g_ad[NN];
__device__ int   g_deg[NN];
__device__ int   g_off[NN + 1];
__device__ int   g_cur[NN];
__device__ int   g_csr[NEDG];      // src node per dst-sorted edge
__device__ float g_cnt[NG];
__device__ int   g_is32;           // 1 if index tensors are int32, 0 if int64

// ---------------- dtype detection: are indices int32 or int64? --------------
__global__ void k_detect(const void* __restrict__ ei) {
    const long long* p = (const long long*)ei;
    int is32 = 0;
    for (int i = 0; i < 64; i++) {
        long long v = p[i];
        if (v < 0 || v >= NN) { is32 = 1; break; }
    }
    g_is32 = is32;
}

// element-indexed index load, dtype-dispatched, clamped for safety
__device__ __forceinline__ int ld_idx(const void* __restrict__ p, long long i, int is32, int lim) {
    long long v = is32 ? (long long)((const int*)p)[i] : ((const long long*)p)[i];
    if (v < 0) v = 0;
    if (v >= lim) v = lim - 1;
    return (int)v;
}

// ---------------- init: deg=1 (self loop), zero pool accumulators -----------
__global__ void k_init(float* dout) {
    int t = blockIdx.x * blockDim.x + threadIdx.x;
    if (t < NN) g_deg[t] = 1;
    if (t < NG * CH) dout[t] = 0.0f;
    if (t < NG) g_cnt[t] = 0.0f;
}

// ---------------- histogram of dst degrees ----------------------------------
__global__ void k_hist(const void* __restrict__ ei) {
    int t = blockIdx.x * blockDim.x + threadIdx.x;
    if (t >= NE) return;
    int is32 = g_is32;
    int d = ld_idx(ei, (long long)NE + t, is32, NN);
    atomicAdd(&g_deg[d], 1);
}

// ---------------- single-block exclusive scan -> offsets + cursors ----------
__global__ void k_scan() {
    __shared__ int sums[1024];
    const int t = threadIdx.x;
    const int CHK = (NN + 1023) / 1024;      // 49
    int b = t * CHK;
    int e = min(NN, b + CHK);
    int s = 0;
    for (int i = b; i < e; i++) s += g_deg[i];
    sums[t] = s;
    __syncthreads();
    for (int o = 1; o < 1024; o <<= 1) {
        int v = 0;
        if (t >= o) v = sums[t - o];
        __syncthreads();
        if (t >= o) sums[t] += v;
        __syncthreads();
    }
    int pre = (t == 0) ? 0 : sums[t - 1];
    for (int i = b; i < e; i++) {
        int d = g_deg[i];
        g_off[i] = pre;
        g_cur[i] = pre;
        pre += d;
    }
    if (t == 1023) g_off[NN] = pre;   // == NEDG
}

// ---------------- scatter edges (incl self loops) into CSR ------------------
__global__ void k_scatter(const void* __restrict__ ei) {
    int t = blockIdx.x * blockDim.x + threadIdx.x;
    if (t >= NEDG) return;
    int is32 = g_is32;
    if (t < NE) {
        int d = ld_idx(ei, (long long)NE + t, is32, NN);
        int s = ld_idx(ei, (long long)t, is32, NN);
        int p = atomicAdd(&g_cur[d], 1);
        g_csr[p] = s;
    } else {
        int i = t - NE;
        int p = atomicAdd(&g_cur[i], 1);
        g_csr[p] = i;                 // self loop
    }
}

// ---------------- h = X @ W; as = h.a_src; ad = h.a_dst  (warp per node) ----
template <bool FIRST>
__global__ void k_gemm(const float* __restrict__ X,
                       const float* __restrict__ W,
                       const float* __restrict__ a_src,
                       const float* __restrict__ a_dst) {
    __shared__ float Ws[CH * CH];
    __shared__ float asv[CH], adv[CH];
    const int tid = threadIdx.x;
    for (int i = tid; i < CH * CH; i += blockDim.x) Ws[i] = W[i];
    if (tid < CH) { asv[tid] = a_src[tid]; adv[tid] = a_dst[tid]; }
    __syncthreads();

    const float* __restrict__ Xp = FIRST ? X : g_out;
    const int lane = tid & 31;
    const int warp = (blockIdx.x * blockDim.x + tid) >> 5;
    const int nwarps = (gridDim.x * blockDim.x) >> 5;

    for (int i = warp; i < NN; i += nwarps) {
        float x_lo = Xp[i * CH + lane];
        float x_hi = Xp[i * CH + lane + 32];
        float acc0 = 0.f, acc1 = 0.f;
        #pragma unroll
        for (int k = 0; k < 32; k++) {
            float xk = __shfl_sync(0xffffffffu, x_lo, k);
            acc0 = fmaf(xk, Ws[k * CH + lane], acc0);
            acc1 = fmaf(xk, Ws[k * CH + lane + 32], acc1);
        }
        #pragma unroll
        for (int k = 0; k < 32; k++) {
            float xk = __shfl_sync(0xffffffffu, x_hi, k);
            acc0 = fmaf(xk, Ws[(k + 32) * CH + lane], acc0);
            acc1 = fmaf(xk, Ws[(k + 32) * CH + lane + 32], acc1);
        }
        g_h[i * CH + lane]      = acc0;
        g_h[i * CH + lane + 32] = acc1;

        float ps = acc0 * asv[lane] + acc1 * asv[lane + 32];
        float pd = acc0 * adv[lane] + acc1 * adv[lane + 32];
        #pragma unroll
        for (int o = 16; o; o >>= 1) {
            ps += __shfl_xor_sync(0xffffffffu, ps, o);
            pd += __shfl_xor_sync(0xffffffffu, pd, o);
        }
        if (lane == 0) { g_as[i] = ps; g_ad[i] = pd; }
    }
}

// ---------------- warp-per-dst: softmax over incoming edges + aggregation ---
__global__ void k_agg(const float* __restrict__ bias) {
    const int w = (blockIdx.x * blockDim.x + threadIdx.x) >> 5;
    const int lane = threadIdx.x & 31;
    if (w >= NN) return;

    const int beg = g_off[w];
    const int end = g_off[w + 1];
    const float adi = g_ad[w];

    // pass 1: online softmax (per-lane strided, then warp combine)
    float m = -1e30f, s = 0.f;
    for (int e = beg + lane; e < end; e += 32) {
        int sn = g_csr[e];
        float l = g_as[sn] + adi;
        l = (l >= 0.f) ? l : 0.2f * l;
        float mn = fmaxf(m, l);
        s = s * __expf(m - mn) + __expf(l - mn);
        m = mn;
    }
    #pragma unroll
    for (int o = 16; o; o >>= 1) {
        float m2 = __shfl_xor_sync(0xffffffffu, m, o);
        float s2 = __shfl_xor_sync(0xffffffffu, s, o);
        float M = fmaxf(m, m2);
        s = s * __expf(m - M) + s2 * __expf(m2 - M);
        m = M;
    }
    const float inv = 1.0f / s;   // s > 0 guaranteed (self loop)

    // pass 2: weighted gather of h[src] rows
    float a0 = 0.f, a1 = 0.f;
    for (int base = beg; base < end; base += 32) {
        int n = min(32, end - base);
        int sn = 0;
        float wgt = 0.f;
        if (lane < n) {
            sn = g_csr[base + lane];
            float l = g_as[sn] + adi;
            l = (l >= 0.f) ? l : 0.2f * l;
            wgt = __expf(l - m) * inv;
        }
        for (int j = 0; j < n; j++) {
            int   sj = __shfl_sync(0xffffffffu, sn, j);
            float wj = __shfl_sync(0xffffffffu, wgt, j);
            a0 = fmaf(wj, g_h[sj * CH + lane], a0);
            a1 = fmaf(wj, g_h[sj * CH + lane + 32], a1);
        }
    }
    a0 += bias[lane];
    a1 += bias[lane + 32];
    a0 = (a0 > 0.f) ? a0 : expm1f(a0);   // elu
    a1 = (a1 > 0.f) ? a1 : expm1f(a1);
    g_out[w * CH + lane]      = a0;
    g_out[w * CH + lane + 32] = a1;
}

// ---------------- global mean pool ------------------------------------------
__global__ void k_pool(const void* __restrict__ batch, float* __restrict__ dout) {
    int t = blockIdx.x * blockDim.x + threadIdx.x;
    if (t >= NN * CH) return;
    int is32 = g_is32;
    int i = t >> 6;
    int c = t & 63;
    int g = ld_idx(batch, i, is32, NG);
    atomicAdd(&dout[g * CH + c], g_out[t]);
    if (c == 0) atomicAdd(&g_cnt[g], 1.0f);
}

__global__ void k_div(float* __restrict__ dout) {
    int t = blockIdx.x * blockDim.x + threadIdx.x;
    if (t < NG * CH) dout[t] *= 1.0f / fmaxf(g_cnt[t >> 6], 1.0f);
}

// ---------------- entry ------------------------------------------------------
extern "C" void kernel_launch(void* const* d_in, const int* in_sizes, int n_in,
                              void* d_out, int out_size) {
    const float* x     = (const float*)d_in[0];
    const void*  ei    = d_in[1];
    const void*  batch = d_in[2];
    const float* W1    = (const float*)d_in[3];
    const float* as1   = (const float*)d_in[4];
    const float* ad1   = (const float*)d_in[5];
    const float* b1    = (const float*)d_in[6];
    const float* W2    = (const float*)d_in[7];
    const float* as2   = (const float*)d_in[8];
    const float* ad2   = (const float*)d_in[9];
    const float* b2    = (const float*)d_in[10];
    float* dout = (float*)d_out;

    k_detect<<<1, 1>>>(ei);
    k_init<<<(NN + 255) / 256, 256>>>(dout);
    k_hist<<<(NE + 255) / 256, 256>>>(ei);
    k_scan<<<1, 1024>>>();
    k_scatter<<<(NEDG + 255) / 256, 256>>>(ei);

    // layer 1
    k_gemm<true><<<592, 256>>>(x, W1, as1, ad1);
    k_agg<<<(NN * 32 + 255) / 256, 256>>>(b1);

    // layer 2 (input = g_out)
    k_gemm<false><<<592, 256>>>(nullptr, W2, as2, ad2);
    k_agg<<<(NN * 32 + 255) / 256, 256>>>(b2);

    // pool
    k_pool<<<(NN * CH + 255) / 256, 256>>>(batch, dout);
    k_div<<<(NG * CH + 255) / 256, 256>>>(dout);
}

// round 3
// speedup vs baseline: 1.3755x; 1.3755x over previous
#include <cuda_runtime.h>

#define NN   50000
#define NE   800000
#define NEDG (NE + NN)
#define NG   512
#define CH   64
#define NB   ((NN + 255) / 256)   // 196 scan blocks

// ---------------- scratch (device globals; no allocations allowed) ----------
__device__ float g_h[NN * CH];     // per-layer h = X @ W
__device__ float g_out[NN * CH];   // per-layer aggregated + elu output
__device__ float g_as[NN];
__device__ float g_ad[NN];
__device__ int   g_deg[NN];
__device__ int   g_off[NN + 1];
__device__ int   g_cur[NN];
__device__ int   g_csr[NEDG];      // src node per dst-sorted edge
__device__ float g_cnt[NG];
__device__ int   g_is32;           // 1 if index tensors are int32, 0 if int64
__device__ int   g_bsum[NB];
__device__ int   g_bpre[NB];

// ---------------- dtype detection: are indices int32 or int64? --------------
__global__ void k_detect(const void* __restrict__ ei) {
    const long long* p = (const long long*)ei;
    int t = threadIdx.x;                      // 32 threads
    long long v0 = p[t];
    long long v1 = p[t + 32];
    int bad = (v0 < 0 || v0 >= NN || v1 < 0 || v1 >= NN);
    unsigned any = __ballot_sync(0xffffffffu, bad);
    if (t == 0) g_is32 = (any != 0u) ? 1 : 0;
}

// element-indexed index load, dtype-dispatched, clamped for safety
__device__ __forceinline__ int ld_idx(const void* __restrict__ p, long long i, int is32, int lim) {
    long long v = is32 ? (long long)((const int*)p)[i] : ((const long long*)p)[i];
    if (v < 0) v = 0;
    if (v >= lim) v = lim - 1;
    return (int)v;
}

// ---------------- init: deg=1 (self loop), zero pool accumulators -----------
__global__ void k_init(float* dout) {
    int t = blockIdx.x * blockDim.x + threadIdx.x;
    if (t < NN) g_deg[t] = 1;
    if (t < NG * CH) dout[t] = 0.0f;
    if (t < NG) g_cnt[t] = 0.0f;
}

// ---------------- histogram of dst degrees ----------------------------------
__global__ void k_hist(const void* __restrict__ ei) {
    int t = blockIdx.x * blockDim.x + threadIdx.x;
    if (t >= NE) return;
    int is32 = g_is32;
    int d = ld_idx(ei, (long long)NE + t, is32, NN);
    atomicAdd(&g_deg[d], 1);
}

// ---------------- 3-phase parallel exclusive scan ----------------------------
// phase A: per-block (256-wide) scan; write local-exclusive to g_off, total to g_bsum
__global__ void k_scan_a() {
    const int t = threadIdx.x;
    const int i = blockIdx.x * 256 + t;
    const int lane = t & 31, wid = t >> 5;
    int d = (i < NN) ? g_deg[i] : 0;
    int v = d;
    #pragma unroll
    for (int o = 1; o < 32; o <<= 1) {
        int u = __shfl_up_sync(0xffffffffu, v, o);
        if (lane >= o) v += u;
    }
    __shared__ int ws[8];
    if (lane == 31) ws[wid] = v;
    __syncthreads();
    if (t < 8) {
        int u = ws[t];
        #pragma unroll
        for (int o = 1; o < 8; o <<= 1) {
            int w2 = __shfl_up_sync(0xffu, u, o);
            if (t >= o) u += w2;
        }
        ws[t] = u;
    }
    __syncthreads();
    int incl = v + (wid ? ws[wid - 1] : 0);
    if (i < NN) g_off[i] = incl - d;           // block-local exclusive
    if (t == 255) g_bsum[blockIdx.x] = incl;   // block total
}

// phase B: single block scans the NB block totals (exclusive)
__global__ void k_scan_b() {
    const int t = threadIdx.x;                 // 256 threads
    const int lane = t & 31, wid = t >> 5;
    int d = (t < NB) ? g_bsum[t] : 0;
    int v = d;
    #pragma unroll
    for (int o = 1; o < 32; o <<= 1) {
        int u = __shfl_up_sync(0xffffffffu, v, o);
        if (lane >= o) v += u;
    }
    __shared__ int ws[8];
    if (lane == 31) ws[wid] = v;
    __syncthreads();
    if (t < 8) {
        int u = ws[t];
        #pragma unroll
        for (int o = 1; o < 8; o <<= 1) {
            int w2 = __shfl_up_sync(0xffu, u, o);
            if (t >= o) u += w2;
        }
        ws[t] = u;
    }
    __syncthreads();
    int incl = v + (wid ? ws[wid - 1] : 0);
    if (t < NB) g_bpre[t] = incl - d;
    if (t == 255) g_off[NN] = incl;            // == NEDG
}

// phase C: add block prefixes, materialize offsets + cursors
__global__ void k_scan_c() {
    int i = blockIdx.x * 256 + threadIdx.x;
    if (i >= NN) return;
    int o = g_off[i] + g_bpre[blockIdx.x];
    g_off[i] = o;
    g_cur[i] = o;
}

// ---------------- scatter edges (incl self loops) into CSR ------------------
__global__ void k_scatter(const void* __restrict__ ei) {
    int t = blockIdx.x * blockDim.x + threadIdx.x;
    if (t >= NEDG) return;
    int is32 = g_is32;
    if (t < NE) {
        int d = ld_idx(ei, (long long)NE + t, is32, NN);
        int s = ld_idx(ei, (long long)t, is32, NN);
        int p = atomicAdd(&g_cur[d], 1);
        g_csr[p] = s;
    } else {
        int i = t - NE;
        int p = atomicAdd(&g_cur[i], 1);
        g_csr[p] = i;                 // self loop
    }
}

// ---------------- h = X @ W; as = h.a_src; ad = h.a_dst  (warp per node) ----
template <bool FIRST>
__global__ void k_gemm(const float* __restrict__ X,
                       const float* __restrict__ W,
                       const float* __restrict__ a_src,
                       const float* __restrict__ a_dst) {
    __shared__ float Ws[CH * CH];
    __shared__ float asv[CH], adv[CH];
    const int tid = threadIdx.x;
    for (int i = tid; i < CH * CH; i += blockDim.x) Ws[i] = W[i];
    if (tid < CH) { asv[tid] = a_src[tid]; adv[tid] = a_dst[tid]; }
    __syncthreads();

    const float* __restrict__ Xp = FIRST ? X : g_out;
    const int lane = tid & 31;
    const int warp = (blockIdx.x * blockDim.x + tid) >> 5;
    const int nwarps = (gridDim.x * blockDim.x) >> 5;

    for (int i = warp; i < NN; i += nwarps) {
        float x_lo = Xp[i * CH + lane];
        float x_hi = Xp[i * CH + lane + 32];
        float acc0 = 0.f, acc1 = 0.f;
        #pragma unroll
        for (int k = 0; k < 32; k++) {
            float xk = __shfl_sync(0xffffffffu, x_lo, k);
            acc0 = fmaf(xk, Ws[k * CH + lane], acc0);
            acc1 = fmaf(xk, Ws[k * CH + lane + 32], acc1);
        }
        #pragma unroll
        for (int k = 0; k < 32; k++) {
            float xk = __shfl_sync(0xffffffffu, x_hi, k);
            acc0 = fmaf(xk, Ws[(k + 32) * CH + lane], acc0);
            acc1 = fmaf(xk, Ws[(k + 32) * CH + lane + 32], acc1);
        }
        g_h[i * CH + lane]      = acc0;
        g_h[i * CH + lane + 32] = acc1;

        float ps = acc0 * asv[lane] + acc1 * asv[lane + 32];
        float pd = acc0 * adv[lane] + acc1 * adv[lane + 32];
        #pragma unroll
        for (int o = 16; o; o >>= 1) {
            ps += __shfl_xor_sync(0xffffffffu, ps, o);
            pd += __shfl_xor_sync(0xffffffffu, pd, o);
        }
        if (lane == 0) { g_as[i] = ps; g_ad[i] = pd; }
    }
}

// ---------------- warp-per-dst: softmax over incoming edges + aggregation ---
__global__ void k_agg(const float* __restrict__ bias) {
    const int w = (blockIdx.x * blockDim.x + threadIdx.x) >> 5;
    const int lane = threadIdx.x & 31;
    if (w >= NN) return;

    const int beg = g_off[w];
    const int end = g_off[w + 1];
    const float adi = g_ad[w];

    // pass 1: online softmax (per-lane strided, then warp combine)
    float m = -1e30f, s = 0.f;
    for (int e = beg + lane; e < end; e += 32) {
        int sn = g_csr[e];
        float l = g_as[sn] + adi;
        l = (l >= 0.f) ? l : 0.2f * l;
        float mn = fmaxf(m, l);
        s = s * __expf(m - mn) + __expf(l - mn);
        m = mn;
    }
    #pragma unroll
    for (int o = 16; o; o >>= 1) {
        float m2 = __shfl_xor_sync(0xffffffffu, m, o);
        float s2 = __shfl_xor_sync(0xffffffffu, s, o);
        float M = fmaxf(m, m2);
        s = s * __expf(m - M) + s2 * __expf(m2 - M);
        m = M;
    }
    const float inv = 1.0f / s;   // s > 0 guaranteed (self loop)

    // pass 2: weighted gather of h[src] rows
    float a0 = 0.f, a1 = 0.f;
    for (int base = beg; base < end; base += 32) {
        int n = min(32, end - base);
        int sn = 0;
        float wgt = 0.f;
        if (lane < n) {
            sn = g_csr[base + lane];
            float l = g_as[sn] + adi;
            l = (l >= 0.f) ? l : 0.2f * l;
            wgt = __expf(l - m) * inv;
        }
        for (int j = 0; j < n; j++) {
            int   sj = __shfl_sync(0xffffffffu, sn, j);
            float wj = __shfl_sync(0xffffffffu, wgt, j);
            a0 = fmaf(wj, g_h[sj * CH + lane], a0);
            a1 = fmaf(wj, g_h[sj * CH + lane + 32], a1);
        }
    }
    a0 += bias[lane];
    a1 += bias[lane + 32];
    a0 = (a0 > 0.f) ? a0 : expm1f(a0);   // elu
    a1 = (a1 > 0.f) ? a1 : expm1f(a1);
    g_out[w * CH + lane]      = a0;
    g_out[w * CH + lane + 32] = a1;
}

// ---------------- global mean pool ------------------------------------------
__global__ void k_pool(const void* __restrict__ batch, float* __restrict__ dout) {
    int t = blockIdx.x * blockDim.x + threadIdx.x;
    if (t >= NN * CH) return;
    int is32 = g_is32;
    int i = t >> 6;
    int c = t & 63;
    int g = ld_idx(batch, i, is32, NG);
    atomicAdd(&dout[g * CH + c], g_out[t]);
    if (c == 0) atomicAdd(&g_cnt[g], 1.0f);
}

__global__ void k_div(float* __restrict__ dout) {
    int t = blockIdx.x * blockDim.x + threadIdx.x;
    if (t < NG * CH) dout[t] *= 1.0f / fmaxf(g_cnt[t >> 6], 1.0f);
}

// ---------------- entry ------------------------------------------------------
extern "C" void kernel_launch(void* const* d_in, const int* in_sizes, int n_in,
                              void* d_out, int out_size) {
    const float* x     = (const float*)d_in[0];
    const void*  ei    = d_in[1];
    const void*  batch = d_in[2];
    const float* W1    = (const float*)d_in[3];
    const float* as1   = (const float*)d_in[4];
    const float* ad1   = (const float*)d_in[5];
    const float* b1    = (const float*)d_in[6];
    const float* W2    = (const float*)d_in[7];
    const float* as2   = (const float*)d_in[8];
    const float* ad2   = (const float*)d_in[9];
    const float* b2    = (const float*)d_in[10];
    float* dout = (float*)d_out;

    k_detect<<<1, 32>>>(ei);
    k_init<<<(NN + 255) / 256, 256>>>(dout);
    k_hist<<<(NE + 255) / 256, 256>>>(ei);
    k_scan_a<<<NB, 256>>>();
    k_scan_b<<<1, 256>>>();
    k_scan_c<<<NB, 256>>>();
    k_scatter<<<(NEDG + 255) / 256, 256>>>(ei);

    // layer 1
    k_gemm<true><<<592, 256>>>(x, W1, as1, ad1);
    k_agg<<<(NN * 32 + 255) / 256, 256>>>(b1);

    // layer 2 (input = g_out)
    k_gemm<false><<<592, 256>>>(nullptr, W2, as2, ad2);
    k_agg<<<(NN * 32 + 255) / 256, 256>>>(b2);

    // pool
    k_pool<<<(NN * CH + 255) / 256, 256>>>(batch, dout);
    k_div<<<(NG * CH + 255) / 256, 256>>>(dout);
}

// round 4
// speedup vs baseline: 1.4547x; 1.0575x over previous
#include <cuda_runtime.h>

#define NN   50000
#define NE   800000
#define NEDG (NE + NN)
#define NG   512
#define CH   64
#define NB   ((NN + 255) / 256)   // 196 scan blocks
#define FULL 0xffffffffu

// ---------------- scratch (device globals; no allocations allowed) ----------
__device__ float2 g_h[NN * 32];    // per-layer h = X @ W  (row = 32 float2)
__device__ float2 g_out[NN * 32];  // per-layer aggregated + elu output
__device__ float g_as[NN];
__device__ float g_ad[NN];
__device__ int   g_deg[NN];
__device__ int   g_off[NN + 1];
__device__ int   g_cur[NN];
__device__ int   g_csr[NEDG];      // src node per dst-sorted edge
__device__ float g_cnt[NG];
__device__ int   g_is32;           // 1 if index tensors are int32, 0 if int64
__device__ int   g_bsum[NB];
__device__ int   g_bpre[NB];

// element-indexed index load, dtype-dispatched, clamped for safety
__device__ __forceinline__ int ld_idx(const void* __restrict__ p, long long i, int is32, int lim) {
    long long v = is32 ? (long long)((const int*)p)[i] : ((const long long*)p)[i];
    if (v < 0) v = 0;
    if (v >= lim) v = lim - 1;
    return (int)v;
}

// ---------------- init (+ dtype detect in block 0) ---------------------------
__global__ void k_init(float* dout, const void* __restrict__ ei) {
    int t = blockIdx.x * blockDim.x + threadIdx.x;
    if (blockIdx.x == 0 && threadIdx.x < 32) {
        const long long* p = (const long long*)ei;
        long long v0 = p[threadIdx.x];
        long long v1 = p[threadIdx.x + 32];
        int bad = (v0 < 0 || v0 >= NN || v1 < 0 || v1 >= NN);
        unsigned any = __ballot_sync(FULL, bad);
        if (threadIdx.x == 0) g_is32 = (any != 0u) ? 1 : 0;
    }
    if (t < NN) g_deg[t] = 1;
    if (t < NG * CH) dout[t] = 0.0f;
    if (t < NG) g_cnt[t] = 0.0f;
}

// ---------------- histogram of dst degrees ----------------------------------
__global__ void k_hist(const void* __restrict__ ei) {
    int t = blockIdx.x * blockDim.x + threadIdx.x;
    if (t >= NE) return;
    int is32 = g_is32;
    int d = ld_idx(ei, (long long)NE + t, is32, NN);
    atomicAdd(&g_deg[d], 1);
}

// ---------------- 3-phase parallel exclusive scan ----------------------------
__global__ void k_scan_a() {
    const int t = threadIdx.x;
    const int i = blockIdx.x * 256 + t;
    const int lane = t & 31, wid = t >> 5;
    int d = (i < NN) ? g_deg[i] : 0;
    int v = d;
    #pragma unroll
    for (int o = 1; o < 32; o <<= 1) {
        int u = __shfl_up_sync(FULL, v, o);
        if (lane >= o) v += u;
    }
    __shared__ int ws[8];
    if (lane == 31) ws[wid] = v;
    __syncthreads();
    if (t < 8) {
        int u = ws[t];
        #pragma unroll
        for (int o = 1; o < 8; o <<= 1) {
            int w2 = __shfl_up_sync(0xffu, u, o);
            if (t >= o) u += w2;
        }
        ws[t] = u;
    }
    __syncthreads();
    int incl = v + (wid ? ws[wid - 1] : 0);
    if (i < NN) g_off[i] = incl - d;
    if (t == 255) g_bsum[blockIdx.x] = incl;
}

__global__ void k_scan_b() {
    const int t = threadIdx.x;                 // 256 threads
    const int lane = t & 31, wid = t >> 5;
    int d = (t < NB) ? g_bsum[t] : 0;
    int v = d;
    #pragma unroll
    for (int o = 1; o < 32; o <<= 1) {
        int u = __shfl_up_sync(FULL, v, o);
        if (lane >= o) v += u;
    }
    __shared__ int ws[8];
    if (lane == 31) ws[wid] = v;
    __syncthreads();
    if (t < 8) {
        int u = ws[t];
        #pragma unroll
        for (int o = 1; o < 8; o <<= 1) {
            int w2 = __shfl_up_sync(0xffu, u, o);
            if (t >= o) u += w2;
        }
        ws[t] = u;
    }
    __syncthreads();
    int incl = v + (wid ? ws[wid - 1] : 0);
    if (t < NB) g_bpre[t] = incl - d;
    if (t == 255) g_off[NN] = incl;
}

__global__ void k_scan_c() {
    int i = blockIdx.x * 256 + threadIdx.x;
    if (i >= NN) return;
    int o = g_off[i] + g_bpre[blockIdx.x];
    g_off[i] = o;
    g_cur[i] = o;
}

// ---------------- scatter edges (incl self loops) into CSR ------------------
__global__ void k_scatter(const void* __restrict__ ei) {
    int t = blockIdx.x * blockDim.x + threadIdx.x;
    if (t >= NEDG) return;
    int is32 = g_is32;
    if (t < NE) {
        int d = ld_idx(ei, (long long)NE + t, is32, NN);
        int s = ld_idx(ei, (long long)t, is32, NN);
        int p = atomicAdd(&g_cur[d], 1);
        g_csr[p] = s;
    } else {
        int i = t - NE;
        int p = atomicAdd(&g_cur[i], 1);
        g_csr[p] = i;                 // self loop
    }
}

// ---------------- h = X @ W; as = h.a_src; ad = h.a_dst  (warp per node) ----
// lane owns output cols (2*lane, 2*lane+1); rows stored as float2
template <bool FIRST>
__global__ void k_gemm(const float2* __restrict__ X2,
                       const float* __restrict__ W,
                       const float* __restrict__ a_src,
                       const float* __restrict__ a_dst) {
    __shared__ float2 Ws2[CH * 32];
    __shared__ float2 as2[32], ad2[32];
    const int tid = threadIdx.x;
    for (int i = tid; i < CH * 32; i += blockDim.x) Ws2[i] = ((const float2*)W)[i];
    if (tid < 32) {
        as2[tid] = ((const float2*)a_src)[tid];
        ad2[tid] = ((const float2*)a_dst)[tid];
    }
    __syncthreads();

    const float2* __restrict__ Xp = FIRST ? X2 : (const float2*)g_out;
    const int lane = tid & 31;
    const int warp = (blockIdx.x * blockDim.x + tid) >> 5;
    const int nwarps = (gridDim.x * blockDim.x) >> 5;

    for (int i = warp; i < NN; i += nwarps) {
        float2 xv = Xp[i * 32 + lane];
        float acc0 = 0.f, acc1 = 0.f;
        #pragma unroll
        for (int k = 0; k < 32; k++) {
            float xa = __shfl_sync(FULL, xv.x, k);
            float xb = __shfl_sync(FULL, xv.y, k);
            float2 wa = Ws2[(2 * k) * 32 + lane];
            float2 wb = Ws2[(2 * k + 1) * 32 + lane];
            acc0 = fmaf(xa, wa.x, acc0);
            acc1 = fmaf(xa, wa.y, acc1);
            acc0 = fmaf(xb, wb.x, acc0);
            acc1 = fmaf(xb, wb.y, acc1);
        }
        g_h[i * 32 + lane] = make_float2(acc0, acc1);

        float2 av = as2[lane], dv = ad2[lane];
        float ps = acc0 * av.x + acc1 * av.y;
        float pd = acc0 * dv.x + acc1 * dv.y;
        #pragma unroll
        for (int o = 16; o; o >>= 1) {
            ps += __shfl_xor_sync(FULL, ps, o);
            pd += __shfl_xor_sync(FULL, pd, o);
        }
        if (lane == 0) { g_as[i] = ps; g_ad[i] = pd; }
    }
}

// ---------------- warp-per-dst: softmax over incoming edges + aggregation ---
__global__ void k_agg(const float* __restrict__ bias) {
    const int w = (blockIdx.x * blockDim.x + threadIdx.x) >> 5;
    const int lane = threadIdx.x & 31;
    if (w >= NN) return;

    const int beg = g_off[w];
    const int end = g_off[w + 1];
    const int deg = end - beg;
    const float adi = g_ad[w];

    float accx = 0.f, accy = 0.f;

    if (deg <= 128) {
        // -------- fast path: edge list cached in registers --------
        const int nch = (deg + 31) >> 5;
        int   sn_r[4];
        float l_r[4];
        float m = -1e30f, s = 0.f;
        #pragma unroll
        for (int c = 0; c < 4; c++) {
            int e = beg + c * 32 + lane;
            int valid = (c < nch) && (e < end);
            int sn = 0;
            float l = -1e30f;
            if (valid) {
                sn = g_csr[e];
                l = g_as[sn] + adi;
                l = (l >= 0.f) ? l : 0.2f * l;
            }
            sn_r[c] = sn;
            l_r[c]  = l;
            float mn = fmaxf(m, l);
            s = s * __expf(m - mn) + (valid ? __expf(l - mn) : 0.f);
            m = mn;
        }
        #pragma unroll
        for (int o = 16; o; o >>= 1) {
            float m2 = __shfl_xor_sync(FULL, m, o);
            float s2 = __shfl_xor_sync(FULL, s, o);
            float M = fmaxf(m, m2);
            s = s * __expf(m - M) + s2 * __expf(m2 - M);
            m = M;
        }
        const float inv = 1.0f / s;

        #pragma unroll
        for (int c = 0; c < 4; c++) {
            if (c >= nch) continue;
            int base = beg + c * 32;
            int n = min(32, end - base);
            float wgt = __expf(l_r[c] - m) * inv;   // invalid lanes -> exp(-huge) = 0
            int sn = sn_r[c];
            int j = 0;
            for (; j + 4 <= n; j += 4) {
                int   s0 = __shfl_sync(FULL, sn, j);
                int   s1 = __shfl_sync(FULL, sn, j + 1);
                int   s2 = __shfl_sync(FULL, sn, j + 2);
                int   s3 = __shfl_sync(FULL, sn, j + 3);
                float w0 = __shfl_sync(FULL, wgt, j);
                float w1 = __shfl_sync(FULL, wgt, j + 1);
                float w2 = __shfl_sync(FULL, wgt, j + 2);
                float w3 = __shfl_sync(FULL, wgt, j + 3);
                float2 v0 = g_h[s0 * 32 + lane];
                float2 v1 = g_h[s1 * 32 + lane];
                float2 v2 = g_h[s2 * 32 + lane];
                float2 v3 = g_h[s3 * 32 + lane];
                accx = fmaf(w0, v0.x, accx);
                accy = fmaf(w0, v0.y, accy);
                accx = fmaf(w1, v1.x, accx);
                accy = fmaf(w1, v1.y, accy);
                accx = fmaf(w2, v2.x, accx);
                accy = fmaf(w2, v2.y, accy);
                accx = fmaf(w3, v3.x, accx);
                accy = fmaf(w3, v3.y, accy);
            }
            for (; j < n; j++) {
                int   sj = __shfl_sync(FULL, sn, j);
                float wj = __shfl_sync(FULL, wgt, j);
                float2 v = g_h[sj * 32 + lane];
                accx = fmaf(wj, v.x, accx);
                accy = fmaf(wj, v.y, accy);
            }
        }
    } else {
        // -------- fallback: recompute path (arbitrary degree) --------
        float m = -1e30f, s = 0.f;
        for (int e = beg + lane; e < end; e += 32) {
            int sn = g_csr[e];
            float l = g_as[sn] + adi;
            l = (l >= 0.f) ? l : 0.2f * l;
            float mn = fmaxf(m, l);
            s = s * __expf(m - mn) + __expf(l - mn);
            m = mn;
        }
        #pragma unroll
        for (int o = 16; o; o >>= 1) {
            float m2 = __shfl_xor_sync(FULL, m, o);
            float s2 = __shfl_xor_sync(FULL, s, o);
            float M = fmaxf(m, m2);
            s = s * __expf(m - M) + s2 * __expf(m2 - M);
            m = M;
        }
        const float inv = 1.0f / s;

        for (int base = beg; base < end; base += 32) {
            int n = min(32, end - base);
            int sn = 0;
            float wgt = 0.f;
            if (lane < n) {
                sn = g_csr[base + lane];
                float l = g_as[sn] + adi;
                l = (l >= 0.f) ? l : 0.2f * l;
                wgt = __expf(l - m) * inv;
            }
            for (int j = 0; j < n; j++) {
                int   sj = __shfl_sync(FULL, sn, j);
                float wj = __shfl_sync(FULL, wgt, j);
                float2 v = g_h[sj * 32 + lane];
                accx = fmaf(wj, v.x, accx);
                accy = fmaf(wj, v.y, accy);
            }
        }
    }

    float2 bv = ((const float2*)bias)[lane];
    accx += bv.x;
    accy += bv.y;
    accx = (accx > 0.f) ? accx : expm1f(accx);   // elu
    accy = (accy > 0.f) ? accy : expm1f(accy);
    g_out[w * 32 + lane] = make_float2(accx, accy);
}

// ---------------- global mean pool (run-length batched atomics) -------------
#define PNODES 8
#define NGRP   ((NN + PNODES - 1) / PNODES)
__global__ void k_pool(const void* __restrict__ batch, float* __restrict__ dout) {
    int t = blockIdx.x * blockDim.x + threadIdx.x;
    if (t >= NGRP * CH) return;
    int c  = t & 63;
    int gi = t >> 6;
    int i0 = gi * PNODES;
    int is32 = g_is32;
    const float* go = (const float*)g_out;

    int gprev = ld_idx(batch, i0, is32, NG);
    float acc = 0.f, cnt = 0.f;
    #pragma unroll
    for (int k = 0; k < PNODES; k++) {
        int i = i0 + k;
        if (i >= NN) break;
        int g = ld_idx(batch, i, is32, NG);
        if (g != gprev) {
            atomicAdd(&dout[gprev * CH + c], acc);
            if (c == 0) atomicAdd(&g_cnt[gprev], cnt);
            acc = 0.f; cnt = 0.f; gprev = g;
        }
        acc += go[i * CH + c];
        cnt += 1.f;
    }
    atomicAdd(&dout[gprev * CH + c], acc);
    if (c == 0) atomicAdd(&g_cnt[gprev], cnt);
}

__global__ void k_div(float* __restrict__ dout) {
    int t = blockIdx.x * blockDim.x + threadIdx.x;
    if (t < NG * CH) dout[t] *= 1.0f / fmaxf(g_cnt[t >> 6], 1.0f);
}

// ---------------- entry ------------------------------------------------------
extern "C" void kernel_launch(void* const* d_in, const int* in_sizes, int n_in,
                              void* d_out, int out_size) {
    const float* x     = (const float*)d_in[0];
    const void*  ei    = d_in[1];
    const void*  batch = d_in[2];
    const float* W1    = (const float*)d_in[3];
    const float* as1   = (const float*)d_in[4];
    const float* ad1   = (const float*)d_in[5];
    const float* b1    = (const float*)d_in[6];
    const float* W2    = (const float*)d_in[7];
    const float* as2   = (const float*)d_in[8];
    const float* ad2   = (const float*)d_in[9];
    const float* b2    = (const float*)d_in[10];
    float* dout = (float*)d_out;

    k_init<<<(NN + 255) / 256, 256>>>(dout, ei);
    k_hist<<<(NE + 255) / 256, 256>>>(ei);
    k_scan_a<<<NB, 256>>>();
    k_scan_b<<<1, 256>>>();
    k_scan_c<<<NB, 256>>>();
    k_scatter<<<(NEDG + 255) / 256, 256>>>(ei);

    // layer 1
    k_gemm<true><<<592, 256>>>((const float2*)x, W1, as1, ad1);
    k_agg<<<(NN * 32 + 255) / 256, 256>>>(b1);

    // layer 2 (input = g_out)
    k_gemm<false><<<592, 256>>>(nullptr, W2, as2, ad2);
    k_agg<<<(NN * 32 + 255) / 256, 256>>>(b2);

    // pool
    k_pool<<<(NGRP * CH + 255) / 256, 256>>>(batch, dout);
    k_div<<<(NG * CH + 255) / 256, 256>>>(dout);
}

// round 5
// speedup vs baseline: 1.4835x; 1.0198x over previous
#include <cuda_runtime.h>
#include <cuda_fp16.h>

#define NN   50000
#define NE   800000
#define NEDG (NE + NN)
#define NG   512
#define CH   64
#define NB   ((NN + 255) / 256)   // 196 scan blocks
#define FULL 0xffffffffu

// ---------------- scratch (device globals; no allocations allowed) ----------
__device__ __half2 g_h[NN * 32];   // per-layer h = X @ W  (fp16, row = 32 half2)
__device__ float2 g_out[NN * 32];  // per-layer aggregated + elu output (fp32)
__device__ float g_as[NN];
__device__ float g_ad[NN];
__device__ int   g_deg[NN];        // zeroed by k_scan_a after use (state restore)
__device__ int   g_off[NN + 1];
__device__ int   g_cur[NN];
__device__ int   g_csr[NEDG];      // src node per dst-sorted edge
__device__ float g_pool[NG * CH];  // zeroed by k_hist each launch
__device__ float g_cnt[NG];        // zeroed by k_hist each launch
__device__ int   g_is32;           // 1 if index tensors are int32, 0 if int64
__device__ int   g_bsum[NB];
__device__ int   g_bpre[NB];
__device__ int   g_tick;           // last-block ticket; reset each launch

// element-indexed index load, dtype-dispatched, clamped for safety
__device__ __forceinline__ int ld_idx(const void* __restrict__ p, long long i, int is32, int lim) {
    long long v = is32 ? (long long)((const int*)p)[i] : ((const long long*)p)[i];
    if (v < 0) v = 0;
    if (v >= lim) v = lim - 1;
    return (int)v;
}

// ---------------- dtype detection (tiny) -------------------------------------
__global__ void k_detect(const void* __restrict__ ei) {
    const long long* p = (const long long*)ei;
    int t = threadIdx.x;                      // 32 threads
    long long v0 = p[t];
    long long v1 = p[t + 32];
    int bad = (v0 < 0 || v0 >= NN || v1 < 0 || v1 >= NN);
    unsigned any = __ballot_sync(FULL, bad);
    if (t == 0) g_is32 = (any != 0u) ? 1 : 0;
}

// ---------------- histogram of dst degrees (+ zero pool accumulators) -------
__global__ void k_hist(const void* __restrict__ ei) {
    int t = blockIdx.x * blockDim.x + threadIdx.x;
    if (t < NG * CH) g_pool[t] = 0.0f;
    if (t < NG) g_cnt[t] = 0.0f;
    if (t >= NE) return;
    int is32 = g_is32;
    int d = ld_idx(ei, (long long)NE + t, is32, NN);
    atomicAdd(&g_deg[d], 1);
}

// ---------------- scan phase A + fused phase B (last-block ticket) ----------
__global__ void k_scan_a() {
    const int t = threadIdx.x;
    const int i = blockIdx.x * 256 + t;
    const int lane = t & 31, wid = t >> 5;
    int d = 0;
    if (i < NN) {
        d = g_deg[i] + 1;      // +1 = self loop
        g_deg[i] = 0;          // restore for next launch
    }
    int v = d;
    #pragma unroll
    for (int o = 1; o < 32; o <<= 1) {
        int u = __shfl_up_sync(FULL, v, o);
        if (lane >= o) v += u;
    }
    __shared__ int ws[8];
    if (lane == 31) ws[wid] = v;
    __syncthreads();
    if (t < 8) {
        int u = ws[t];
        #pragma unroll
        for (int o = 1; o < 8; o <<= 1) {
            int w2 = __shfl_up_sync(0xffu, u, o);
            if (t >= o) u += w2;
        }
        ws[t] = u;
    }
    __syncthreads();
    int incl = v + (wid ? ws[wid - 1] : 0);
    if (i < NN) g_off[i] = incl - d;
    if (t == 255) g_bsum[blockIdx.x] = incl;

    // ---- last finishing block performs the block-sum scan (phase B) ----
    __threadfence();
    __shared__ int is_last;
    if (t == 0) {
        int old = atomicAdd(&g_tick, 1);
        is_last = (old == (int)gridDim.x - 1);
    }
    __syncthreads();
    if (!is_last) return;
    __threadfence();

    int d2 = (t < NB) ? g_bsum[t] : 0;
    int v2 = d2;
    #pragma unroll
    for (int o = 1; o < 32; o <<= 1) {
        int u = __shfl_up_sync(FULL, v2, o);
        if (lane >= o) v2 += u;
    }
    __shared__ int ws2[8];
    if (lane == 31) ws2[wid] = v2;
    __syncthreads();
    if (t < 8) {
        int u = ws2[t];
        #pragma unroll
        for (int o = 1; o < 8; o <<= 1) {
            int w2 = __shfl_up_sync(0xffu, u, o);
            if (t >= o) u += w2;
        }
        ws2[t] = u;
    }
    __syncthreads();
    int incl2 = v2 + (wid ? ws2[wid - 1] : 0);
    if (t < NB) g_bpre[t] = incl2 - d2;
    if (t == 255) { g_off[NN] = incl2; g_tick = 0; }
}

// phase C: add block prefixes, materialize offsets + cursors
__global__ void k_scan_c() {
    int i = blockIdx.x * 256 + threadIdx.x;
    if (i >= NN) return;
    int o = g_off[i] + g_bpre[blockIdx.x];
    g_off[i] = o;
    g_cur[i] = o;
}

// ---------------- scatter edges (incl self loops) into CSR ------------------
__global__ void k_scatter(const void* __restrict__ ei) {
    int t = blockIdx.x * blockDim.x + threadIdx.x;
    if (t >= NEDG) return;
    int is32 = g_is32;
    if (t < NE) {
        int d = ld_idx(ei, (long long)NE + t, is32, NN);
        int s = ld_idx(ei, (long long)t, is32, NN);
        int p = atomicAdd(&g_cur[d], 1);
        g_csr[p] = s;
    } else {
        int i = t - NE;
        int p = atomicAdd(&g_cur[i], 1);
        g_csr[p] = i;                 // self loop
    }
}

// ---------------- h = X @ W; as = h.a_src; ad = h.a_dst  (warp per node) ----
template <bool FIRST>
__global__ void k_gemm(const float2* __restrict__ X2,
                       const float* __restrict__ W,
                       const float* __restrict__ a_src,
                       const float* __restrict__ a_dst) {
    __shared__ float2 Ws2[CH * 32];
    __shared__ float2 as2[32], ad2[32];
    const int tid = threadIdx.x;
    for (int i = tid; i < CH * 32; i += blockDim.x) Ws2[i] = ((const float2*)W)[i];
    if (tid < 32) {
        as2[tid] = ((const float2*)a_src)[tid];
        ad2[tid] = ((const float2*)a_dst)[tid];
    }
    __syncthreads();

    const float2* __restrict__ Xp = FIRST ? X2 : (const float2*)g_out;
    const int lane = tid & 31;
    const int warp = (blockIdx.x * blockDim.x + tid) >> 5;
    const int nwarps = (gridDim.x * blockDim.x) >> 5;

    for (int i = warp; i < NN; i += nwarps) {
        float2 xv = Xp[i * 32 + lane];
        float acc0 = 0.f, acc1 = 0.f;
        #pragma unroll
        for (int k = 0; k < 32; k++) {
            float xa = __shfl_sync(FULL, xv.x, k);
            float xb = __shfl_sync(FULL, xv.y, k);
            float2 wa = Ws2[(2 * k) * 32 + lane];
            float2 wb = Ws2[(2 * k + 1) * 32 + lane];
            acc0 = fmaf(xa, wa.x, acc0);
            acc1 = fmaf(xa, wa.y, acc1);
            acc0 = fmaf(xb, wb.x, acc0);
            acc1 = fmaf(xb, wb.y, acc1);
        }
        g_h[i * 32 + lane] = __floats2half2_rn(acc0, acc1);

        float2 av = as2[lane], dv = ad2[lane];
        float ps = acc0 * av.x + acc1 * av.y;
        float pd = acc0 * dv.x + acc1 * dv.y;
        #pragma unroll
        for (int o = 16; o; o >>= 1) {
            ps += __shfl_xor_sync(FULL, ps, o);
            pd += __shfl_xor_sync(FULL, pd, o);
        }
        if (lane == 0) { g_as[i] = ps; g_ad[i] = pd; }
    }
}

// ---------------- warp-per-dst: softmax over incoming edges + aggregation ---
__global__ void k_agg(const float* __restrict__ bias) {
    const int w = (blockIdx.x * blockDim.x + threadIdx.x) >> 5;
    const int lane = threadIdx.x & 31;
    if (w >= NN) return;

    const int beg = g_off[w];
    const int end = g_off[w + 1];
    const int deg = end - beg;
    const float adi = g_ad[w];

    float accx = 0.f, accy = 0.f;

    if (deg <= 128) {
        // -------- fast path: edge list cached in registers --------
        const int nch = (deg + 31) >> 5;
        int   sn_r[4];
        float l_r[4];
        float m = -1e30f, s = 0.f;
        #pragma unroll
        for (int c = 0; c < 4; c++) {
            int e = beg + c * 32 + lane;
            int valid = (c < nch) && (e < end);
            int sn = 0;
            float l = -1e30f;
            if (valid) {
                sn = g_csr[e];
                l = g_as[sn] + adi;
                l = (l >= 0.f) ? l : 0.2f * l;
            }
            sn_r[c] = sn;
            l_r[c]  = l;
            float mn = fmaxf(m, l);
            s = s * __expf(m - mn) + (valid ? __expf(l - mn) : 0.f);
            m = mn;
        }
        #pragma unroll
        for (int o = 16; o; o >>= 1) {
            float m2 = __shfl_xor_sync(FULL, m, o);
            float s2 = __shfl_xor_sync(FULL, s, o);
            float M = fmaxf(m, m2);
            s = s * __expf(m - M) + s2 * __expf(m2 - M);
            m = M;
        }
        const float inv = 1.0f / s;

        #pragma unroll
        for (int c = 0; c < 4; c++) {
            if (c >= nch) continue;
            int base = beg + c * 32;
            int n = min(32, end - base);
            float wgt = __expf(l_r[c] - m) * inv;   // invalid lanes -> 0
            int sn = sn_r[c];
            int j = 0;
            for (; j + 4 <= n; j += 4) {
                int   s0 = __shfl_sync(FULL, sn, j);
                int   s1 = __shfl_sync(FULL, sn, j + 1);
                int   s2 = __shfl_sync(FULL, sn, j + 2);
                int   s3 = __shfl_sync(FULL, sn, j + 3);
                float w0 = __shfl_sync(FULL, wgt, j);
                float w1 = __shfl_sync(FULL, wgt, j + 1);
                float w2 = __shfl_sync(FULL, wgt, j + 2);
                float w3 = __shfl_sync(FULL, wgt, j + 3);
                float2 v0 = __half22float2(g_h[s0 * 32 + lane]);
                float2 v1 = __half22float2(g_h[s1 * 32 + lane]);
                float2 v2 = __half22float2(g_h[s2 * 32 + lane]);
                float2 v3 = __half22float2(g_h[s3 * 32 + lane]);
                accx = fmaf(w0, v0.x, accx);
                accy = fmaf(w0, v0.y, accy);
                accx = fmaf(w1, v1.x, accx);
                accy = fmaf(w1, v1.y, accy);
                accx = fmaf(w2, v2.x, accx);
                accy = fmaf(w2, v2.y, accy);
                accx = fmaf(w3, v3.x, accx);
                accy = fmaf(w3, v3.y, accy);
            }
            for (; j < n; j++) {
                int   sj = __shfl_sync(FULL, sn, j);
                float wj = __shfl_sync(FULL, wgt, j);
                float2 v = __half22float2(g_h[sj * 32 + lane]);
                accx = fmaf(wj, v.x, accx);
                accy = fmaf(wj, v.y, accy);
            }
        }
    } else {
        // -------- fallback: recompute path (arbitrary degree) --------
        float m = -1e30f, s = 0.f;
        for (int e = beg + lane; e < end; e += 32) {
            int sn = g_csr[e];
            float l = g_as[sn] + adi;
            l = (l >= 0.f) ? l : 0.2f * l;
            float mn = fmaxf(m, l);
            s = s * __expf(m - mn) + __expf(l - mn);
            m = mn;
        }
        #pragma unroll
        for (int o = 16; o; o >>= 1) {
            float m2 = __shfl_xor_sync(FULL, m, o);
            float s2 = __shfl_xor_sync(FULL, s, o);
            float M = fmaxf(m, m2);
            s = s * __expf(m - M) + s2 * __expf(m2 - M);
            m = M;
        }
        const float inv = 1.0f / s;

        for (int base = beg; base < end; base += 32) {
            int n = min(32, end - base);
            int sn = 0;
            float wgt = 0.f;
            if (lane < n) {
                sn = g_csr[base + lane];
                float l = g_as[sn] + adi;
                l = (l >= 0.f) ? l : 0.2f * l;
                wgt = __expf(l - m) * inv;
            }
            for (int j = 0; j < n; j++) {
                int   sj = __shfl_sync(FULL, sn, j);
                float wj = __shfl_sync(FULL, wgt, j);
                float2 v = __half22float2(g_h[sj * 32 + lane]);
                accx = fmaf(wj, v.x, accx);
                accy = fmaf(wj, v.y, accy);
            }
        }
    }

    float2 bv = ((const float2*)bias)[lane];
    accx += bv.x;
    accy += bv.y;
    accx = (accx > 0.f) ? accx : expm1f(accx);   // elu
    accy = (accy > 0.f) ? accy : expm1f(accy);
    g_out[w * 32 + lane] = make_float2(accx, accy);
}

// ---------------- global mean pool (warp per 8-node run) ---------------------
#define PNODES 8
#define NGRP   ((NN + PNODES - 1) / PNODES)
__global__ void k_pool(const void* __restrict__ batch) {
    const int wid = (blockIdx.x * blockDim.x + threadIdx.x) >> 5;
    const int lane = threadIdx.x & 31;
    if (wid >= NGRP) return;
    const int i0 = wid * PNODES;
    const int is32 = g_is32;

    int b = 0;
    if (lane < PNODES && i0 + lane < NN) b = ld_idx(batch, i0 + lane, is32, NG);

    int gprev = __shfl_sync(FULL, b, 0);
    float ax = 0.f, ay = 0.f, cnt = 0.f;
    #pragma unroll
    for (int k = 0; k < PNODES; k++) {
        int i = i0 + k;
        if (i >= NN) break;
        int g = __shfl_sync(FULL, b, k);
        if (g != gprev) {
            atomicAdd(&g_pool[gprev * CH + 2 * lane], ax);
            atomicAdd(&g_pool[gprev * CH + 2 * lane + 1], ay);
            if (lane == 0) atomicAdd(&g_cnt[gprev], cnt);
            ax = 0.f; ay = 0.f; cnt = 0.f; gprev = g;
        }
        float2 v = g_out[i * 32 + lane];
        ax += v.x; ay += v.y; cnt += 1.f;
    }
    atomicAdd(&g_pool[gprev * CH + 2 * lane], ax);
    atomicAdd(&g_pool[gprev * CH + 2 * lane + 1], ay);
    if (lane == 0) atomicAdd(&g_cnt[gprev], cnt);
}

__global__ void k_div(float* __restrict__ dout) {
    int t = blockIdx.x * blockDim.x + threadIdx.x;
    if (t >= NG * CH) return;
    dout[t] = g_pool[t] * (1.0f / fmaxf(g_cnt[t >> 6], 1.0f));
}

// ---------------- entry ------------------------------------------------------
extern "C" void kernel_launch(void* const* d_in, const int* in_sizes, int n_in,
                              void* d_out, int out_size) {
    const float* x     = (const float*)d_in[0];
    const void*  ei    = d_in[1];
    const void*  batch = d_in[2];
    const float* W1    = (const float*)d_in[3];
    const float* as1   = (const float*)d_in[4];
    const float* ad1   = (const float*)d_in[5];
    const float* b1    = (const float*)d_in[6];
    const float* W2    = (const float*)d_in[7];
    const float* as2   = (const float*)d_in[8];
    const float* ad2   = (const float*)d_in[9];
    const float* b2    = (const float*)d_in[10];
    float* dout = (float*)d_out;

    k_detect<<<1, 32>>>(ei);
    k_hist<<<(NE + 255) / 256, 256>>>(ei);
    k_scan_a<<<NB, 256>>>();
    k_scan_c<<<NB, 256>>>();
    k_scatter<<<(NEDG + 255) / 256, 256>>>(ei);

    // layer 1
    k_gemm<true><<<592, 256>>>((const float2*)x, W1, as1, ad1);
    k_agg<<<(NN * 32 + 255) / 256, 256>>>(b1);

    // layer 2 (input = g_out)
    k_gemm<false><<<592, 256>>>(nullptr, W2, as2, ad2);
    k_agg<<<(NN * 32 + 255) / 256, 256>>>(b2);

    // pool
    k_pool<<<(NGRP * 32 + 255) / 256, 256>>>(batch);
    k_div<<<(NG * CH + 255) / 256, 256>>>(dout);
}